// round 5
// baseline (speedup 1.0000x reference)
#include <cuda_runtime.h>

#define B_SZ 65536
#define D_SZ 512
#define V4_PER_ROW (D_SZ / 4)              // 128
#define NC 16
#define NBLOCKS 888                        // 148 SMs x 6 CTAs -> exactly one wave
#define NTHREADS 256
#define WARPS_PER_BLOCK (NTHREADS / 32)    // 8
#define TOTAL_WARPS (NBLOCKS * WARPS_PER_BLOCK)   // 7104
#define ROWS_BASE (B_SZ / TOTAL_WARPS)     // 9
#define ROWS_REM (B_SZ - ROWS_BASE * TOTAL_WARPS) // 1600 warps get one extra row
#define NPAIR (NC * (NC - 1) / 2)          // 120
#define PAIRS_PER_WARP (NPAIR / WARPS_PER_BLOCK)  // 15

__device__ float g_partials[NBLOCKS];
__device__ unsigned int g_ticket = 0;      // atomicInc wraps to 0 -> graph-replay safe

__global__ __launch_bounds__(NTHREADS, 6) void k_island_fused(
    const float4* __restrict__ x,
    const int* __restrict__ y,             // int32 (JAX x64 disabled)
    const float4* __restrict__ centers,
    float* __restrict__ out)
{
    __shared__ float4 sc[NC * V4_PER_ROW]; // 32 KB center cache
    __shared__ float ws[WARPS_PER_BLOCK];
    __shared__ double wd[WARPS_PER_BLOCK];
    __shared__ float norms[NC];
    __shared__ float warp_pair[WARPS_PER_BLOCK];
    __shared__ unsigned int s_ticket;

    const int t = threadIdx.x;
    const int lane = t & 31;
    const int wid = t >> 5;

    #pragma unroll
    for (int i = 0; i < (NC * V4_PER_ROW) / NTHREADS; i++)
        sc[i * NTHREADS + t] = centers[i * NTHREADS + t];
    __syncthreads();

    // ---- Phase 1: streaming center-loss partial ----
    // Balanced contiguous row range per warp: first ROWS_REM warps get one extra.
    const int gw = blockIdx.x * WARPS_PER_BLOCK + wid;
    const int extra = (gw < ROWS_REM) ? 1 : 0;
    const int row0 = gw * ROWS_BASE + (extra ? gw : ROWS_REM);
    const int nrows = ROWS_BASE + extra;

    float a0 = 0.f, a1 = 0.f, a2 = 0.f, a3 = 0.f;
    for (int r = 0; r < nrows; r++) {
        const int row = row0 + r;
        const int cls = __ldg(&y[row]) & 15;          // warp-broadcast load
        const float4* __restrict__ xr = x + (size_t)row * V4_PER_ROW;
        // front-batch the 4 global loads for MLP
        float4 xv0 = __ldg(&xr[lane]);
        float4 xv1 = __ldg(&xr[32 + lane]);
        float4 xv2 = __ldg(&xr[64 + lane]);
        float4 xv3 = __ldg(&xr[96 + lane]);
        const float4* __restrict__ cr = sc + (cls << 7);
        float4 cv0 = cr[lane];
        float4 cv1 = cr[32 + lane];
        float4 cv2 = cr[64 + lane];
        float4 cv3 = cr[96 + lane];
        float d;
        d = xv0.x - cv0.x; a0 = fmaf(d, d, a0);
        d = xv0.y - cv0.y; a1 = fmaf(d, d, a1);
        d = xv0.z - cv0.z; a2 = fmaf(d, d, a2);
        d = xv0.w - cv0.w; a3 = fmaf(d, d, a3);
        d = xv1.x - cv1.x; a0 = fmaf(d, d, a0);
        d = xv1.y - cv1.y; a1 = fmaf(d, d, a1);
        d = xv1.z - cv1.z; a2 = fmaf(d, d, a2);
        d = xv1.w - cv1.w; a3 = fmaf(d, d, a3);
        d = xv2.x - cv2.x; a0 = fmaf(d, d, a0);
        d = xv2.y - cv2.y; a1 = fmaf(d, d, a1);
        d = xv2.z - cv2.z; a2 = fmaf(d, d, a2);
        d = xv2.w - cv2.w; a3 = fmaf(d, d, a3);
        d = xv3.x - cv3.x; a0 = fmaf(d, d, a0);
        d = xv3.y - cv3.y; a1 = fmaf(d, d, a1);
        d = xv3.z - cv3.z; a2 = fmaf(d, d, a2);
        d = xv3.w - cv3.w; a3 = fmaf(d, d, a3);
    }
    float acc = (a0 + a1) + (a2 + a3);

    #pragma unroll
    for (int o = 16; o > 0; o >>= 1)
        acc += __shfl_down_sync(0xffffffffu, acc, o);
    if (lane == 0) ws[wid] = acc;
    __syncthreads();
    if (t == 0) {
        float v = 0.f;
        #pragma unroll
        for (int w = 0; w < WARPS_PER_BLOCK; w++) v += ws[w];
        g_partials[blockIdx.x] = v;
        __threadfence();
        s_ticket = atomicInc(&g_ticket, NBLOCKS - 1);
    }
    __syncthreads();
    if (s_ticket != NBLOCKS - 1)
        return;                                       // not the last block

    // ---- Phase 2 (last block only): final reduce + island term ----
    // Partials: fixed-order strided per-thread sums in double, then warp shuffle.
    double s = 0.0;
    #pragma unroll
    for (int i = 0; i < (NBLOCKS + NTHREADS - 1) / NTHREADS; i++) {
        int idx = i * NTHREADS + t;
        if (idx < NBLOCKS) s += (double)g_partials[idx];
    }
    #pragma unroll
    for (int o = 16; o > 0; o >>= 1)
        s += __shfl_down_sync(0xffffffffu, s, o);
    if (lane == 0) wd[wid] = s;

    // Norms: warp-per-2-rows (centers still resident in sc)
    #pragma unroll
    for (int r = 0; r < 2; r++) {
        const int row = wid * 2 + r;
        const float4* cr = sc + (row << 7);
        float ns = 0.0f;
        #pragma unroll
        for (int i = 0; i < 4; i++) {
            float4 v = cr[i * 32 + lane];
            ns += v.x * v.x + v.y * v.y + v.z * v.z + v.w * v.w;
        }
        #pragma unroll
        for (int o = 16; o > 0; o >>= 1)
            ns += __shfl_down_sync(0xffffffffu, ns, o);
        if (lane == 0) norms[row] = sqrtf(ns);
    }
    __syncthreads();

    // Pairs: 15 per warp, fixed order
    float psum = 0.0f;
    #pragma unroll
    for (int pp = 0; pp < PAIRS_PER_WARP; pp++) {
        const int p = wid * PAIRS_PER_WARP + pp;
        int j = 0, rem = p;
        while (rem >= NC - 1 - j) { rem -= NC - 1 - j; j++; }
        const int k = j + 1 + rem;
        const float4* cj = sc + (j << 7);
        const float4* ck = sc + (k << 7);
        float dot = 0.0f;
        #pragma unroll
        for (int i = 0; i < 4; i++) {
            float4 a = cj[i * 32 + lane];
            float4 b = ck[i * 32 + lane];
            dot += a.x * b.x + a.y * b.y + a.z * b.z + a.w * b.w;
        }
        #pragma unroll
        for (int o = 16; o > 0; o >>= 1)
            dot += __shfl_down_sync(0xffffffffu, dot, o);
        if (lane == 0)
            psum += dot / (norms[j] * norms[k] + 1e-9f) + 1.0f;
    }
    if (lane == 0) warp_pair[wid] = psum;
    __syncthreads();

    if (t == 0) {
        double total = 0.0;
        float island = 0.0f;
        #pragma unroll
        for (int w = 0; w < WARPS_PER_BLOCK; w++) {
            total += wd[w];
            island += warp_pair[w];
        }
        // SCALE = 1, LAMDA = 1, LAMDA1 = 10
        float loss_center = 0.5f * (float)total * (1.0f / (float)B_SZ);
        out[0] = loss_center + 10.0f * island;
    }
}

extern "C" void kernel_launch(void* const* d_in, const int* in_sizes, int n_in,
                              void* d_out, int out_size)
{
    // Identify inputs by element count (robust to ordering):
    //   output_features: 65536*512 = 33554432
    //   y_truth:         65536
    //   feature_centers: 16*512   = 8192
    const float4* x = nullptr;
    const int* y = nullptr;
    const float4* centers = nullptr;
    for (int i = 0; i < n_in; i++) {
        if (in_sizes[i] == 33554432)      x = (const float4*)d_in[i];
        else if (in_sizes[i] == 65536)    y = (const int*)d_in[i];
        else if (in_sizes[i] == 8192)     centers = (const float4*)d_in[i];
    }
    float* out = (float*)d_out;

    k_island_fused<<<NBLOCKS, NTHREADS>>>(x, y, centers, out);
}

// round 6
// speedup vs baseline: 1.1141x; 1.1141x over previous
#include <cuda_runtime.h>

#define B_SZ 65536
#define D_SZ 512
#define V4_PER_ROW (D_SZ / 4)              // 128
#define TOTAL_V4 (B_SZ * V4_PER_ROW)       // 8,388,608
#define NC 16
#define NBLOCKS 740                        // 148 SMs x 5 CTAs -> one wave even at 5 CTA/SM
#define NTHREADS 256
#define WARPS_PER_BLOCK (NTHREADS / 32)    // 8
#define GRID_STRIDE (NBLOCKS * NTHREADS)   // 189,440
#define NPAIR (NC * (NC - 1) / 2)          // 120
#define PAIRS_PER_WARP (NPAIR / WARPS_PER_BLOCK)  // 15

__device__ float g_partials[NBLOCKS];
__device__ unsigned int g_ticket = 0;      // atomicInc wraps to 0 -> graph-replay safe

__global__ __launch_bounds__(NTHREADS) void k_island_fused(
    const float4* __restrict__ x,
    const int* __restrict__ y,             // int32 (JAX x64 disabled)
    const float4* __restrict__ centers,
    float* __restrict__ out)
{
    __shared__ float4 sc[NC * V4_PER_ROW]; // 32 KB center cache
    __shared__ float ws[WARPS_PER_BLOCK];
    __shared__ double wd[WARPS_PER_BLOCK];
    __shared__ float norms[NC];
    __shared__ float warp_pair[WARPS_PER_BLOCK];
    __shared__ unsigned int s_ticket;

    const int t = threadIdx.x;
    const int lane = t & 31;
    const int wid = t >> 5;

    #pragma unroll
    for (int i = 0; i < (NC * V4_PER_ROW) / NTHREADS; i++)
        sc[i * NTHREADS + t] = centers[i * NTHREADS + t];
    __syncthreads();

    // ---- Phase 1: streaming center-loss partial ----
    // Grid-stride with explicit 4-way independent unroll for MLP.
    float a0 = 0.f, a1 = 0.f, a2 = 0.f, a3 = 0.f;
    int i0 = blockIdx.x * NTHREADS + t;

    for (; i0 + 3 * GRID_STRIDE < TOTAL_V4; i0 += 4 * GRID_STRIDE) {
        const int i1 = i0 + GRID_STRIDE;
        const int i2 = i0 + 2 * GRID_STRIDE;
        const int i3 = i0 + 3 * GRID_STRIDE;
        // 4 independent global loads + 4 independent label loads (front-batched)
        float4 x0 = __ldg(&x[i0]);
        float4 x1 = __ldg(&x[i1]);
        float4 x2 = __ldg(&x[i2]);
        float4 x3 = __ldg(&x[i3]);
        int c0 = __ldg(&y[i0 >> 7]) & 15;
        int c1 = __ldg(&y[i1 >> 7]) & 15;
        int c2 = __ldg(&y[i2 >> 7]) & 15;
        int c3 = __ldg(&y[i3 >> 7]) & 15;
        float4 v0 = sc[(c0 << 7) + (i0 & 127)];
        float4 v1 = sc[(c1 << 7) + (i1 & 127)];
        float4 v2 = sc[(c2 << 7) + (i2 & 127)];
        float4 v3 = sc[(c3 << 7) + (i3 & 127)];
        float d;
        d = x0.x - v0.x; a0 = fmaf(d, d, a0);
        d = x0.y - v0.y; a1 = fmaf(d, d, a1);
        d = x0.z - v0.z; a2 = fmaf(d, d, a2);
        d = x0.w - v0.w; a3 = fmaf(d, d, a3);
        d = x1.x - v1.x; a0 = fmaf(d, d, a0);
        d = x1.y - v1.y; a1 = fmaf(d, d, a1);
        d = x1.z - v1.z; a2 = fmaf(d, d, a2);
        d = x1.w - v1.w; a3 = fmaf(d, d, a3);
        d = x2.x - v2.x; a0 = fmaf(d, d, a0);
        d = x2.y - v2.y; a1 = fmaf(d, d, a1);
        d = x2.z - v2.z; a2 = fmaf(d, d, a2);
        d = x2.w - v2.w; a3 = fmaf(d, d, a3);
        d = x3.x - v3.x; a0 = fmaf(d, d, a0);
        d = x3.y - v3.y; a1 = fmaf(d, d, a1);
        d = x3.z - v3.z; a2 = fmaf(d, d, a2);
        d = x3.w - v3.w; a3 = fmaf(d, d, a3);
    }
    // tail (at most 3 strided iterations)
    for (; i0 < TOTAL_V4; i0 += GRID_STRIDE) {
        float4 xv = __ldg(&x[i0]);
        int cls = __ldg(&y[i0 >> 7]) & 15;
        float4 cv = sc[(cls << 7) + (i0 & 127)];
        float d;
        d = xv.x - cv.x; a0 = fmaf(d, d, a0);
        d = xv.y - cv.y; a1 = fmaf(d, d, a1);
        d = xv.z - cv.z; a2 = fmaf(d, d, a2);
        d = xv.w - cv.w; a3 = fmaf(d, d, a3);
    }
    float acc = (a0 + a1) + (a2 + a3);

    #pragma unroll
    for (int o = 16; o > 0; o >>= 1)
        acc += __shfl_down_sync(0xffffffffu, acc, o);
    if (lane == 0) ws[wid] = acc;
    __syncthreads();
    if (t == 0) {
        float v = 0.f;
        #pragma unroll
        for (int w = 0; w < WARPS_PER_BLOCK; w++) v += ws[w];
        g_partials[blockIdx.x] = v;
        __threadfence();
        s_ticket = atomicInc(&g_ticket, NBLOCKS - 1);
    }
    __syncthreads();
    if (s_ticket != NBLOCKS - 1)
        return;                                       // not the last block

    // ---- Phase 2 (last block only): final reduce + island term ----
    double s = 0.0;
    for (int i = t; i < NBLOCKS; i += NTHREADS)
        s += (double)g_partials[i];
    #pragma unroll
    for (int o = 16; o > 0; o >>= 1)
        s += __shfl_down_sync(0xffffffffu, s, o);
    if (lane == 0) wd[wid] = s;

    // Norms: warp-per-2-rows (centers still resident in sc)
    #pragma unroll
    for (int r = 0; r < 2; r++) {
        const int row = wid * 2 + r;
        const float4* cr = sc + (row << 7);
        float ns = 0.0f;
        #pragma unroll
        for (int i = 0; i < 4; i++) {
            float4 v = cr[i * 32 + lane];
            ns += v.x * v.x + v.y * v.y + v.z * v.z + v.w * v.w;
        }
        #pragma unroll
        for (int o = 16; o > 0; o >>= 1)
            ns += __shfl_down_sync(0xffffffffu, ns, o);
        if (lane == 0) norms[row] = sqrtf(ns);
    }
    __syncthreads();

    // Pairs: 15 per warp, fixed order
    float psum = 0.0f;
    #pragma unroll
    for (int pp = 0; pp < PAIRS_PER_WARP; pp++) {
        const int p = wid * PAIRS_PER_WARP + pp;
        int j = 0, rem = p;
        while (rem >= NC - 1 - j) { rem -= NC - 1 - j; j++; }
        const int k = j + 1 + rem;
        const float4* cj = sc + (j << 7);
        const float4* ck = sc + (k << 7);
        float dot = 0.0f;
        #pragma unroll
        for (int i = 0; i < 4; i++) {
            float4 a = cj[i * 32 + lane];
            float4 b = ck[i * 32 + lane];
            dot += a.x * b.x + a.y * b.y + a.z * b.z + a.w * b.w;
        }
        #pragma unroll
        for (int o = 16; o > 0; o >>= 1)
            dot += __shfl_down_sync(0xffffffffu, dot, o);
        if (lane == 0)
            psum += dot / (norms[j] * norms[k] + 1e-9f) + 1.0f;
    }
    if (lane == 0) warp_pair[wid] = psum;
    __syncthreads();

    if (t == 0) {
        double total = 0.0;
        float island = 0.0f;
        #pragma unroll
        for (int w = 0; w < WARPS_PER_BLOCK; w++) {
            total += wd[w];
            island += warp_pair[w];
        }
        // SCALE = 1, LAMDA = 1, LAMDA1 = 10
        float loss_center = 0.5f * (float)total * (1.0f / (float)B_SZ);
        out[0] = loss_center + 10.0f * island;
    }
}

extern "C" void kernel_launch(void* const* d_in, const int* in_sizes, int n_in,
                              void* d_out, int out_size)
{
    // Identify inputs by element count (robust to ordering):
    //   output_features: 65536*512 = 33554432
    //   y_truth:         65536
    //   feature_centers: 16*512   = 8192
    const float4* x = nullptr;
    const int* y = nullptr;
    const float4* centers = nullptr;
    for (int i = 0; i < n_in; i++) {
        if (in_sizes[i] == 33554432)      x = (const float4*)d_in[i];
        else if (in_sizes[i] == 65536)    y = (const int*)d_in[i];
        else if (in_sizes[i] == 8192)     centers = (const float4*)d_in[i];
    }
    float* out = (float*)d_out;

    k_island_fused<<<NBLOCKS, NTHREADS>>>(x, y, centers, out);
}